// round 6
// baseline (speedup 1.0000x reference)
#include <cuda_runtime.h>
#include <math.h>

#define BN_ 256      // batch
#define G_  4000     // genes
#define P_  128      // pathways
#define D_  12000    // expert in dim
#define H_  64       // expert hidden
#define O_  16       // expert out
#define GH_ 128      // gate hidden
#define CH_ 8        // classifier hidden
#define C_  5        // classes
#define K_  3        // top_k
#define EPS_ 1e-5f

// ---- gate GEMM1 config ----
#define KS_  20      // K splits
#define KCH_ 200     // 4000 / 20
#define TM_  64
#define TN_  32
#define KT_  8

// ---- expert config ----
#define SCH_ 8       // samples per chunk
#define GT_  500     // gene tile
#define NT_  8       // gene tiles (4000/500)
#define RS_  6       // row splits per item: 3 omics x 2 gene-halves
#define XSTR_ 12     // sX row stride in floats (48B: 16B-aligned, low-conflict)
#define MAXITEMS_ 224

// ---- compaction ----
#define GPB_ 16      // genes owned per thread (256*16 = 4096 >= 4000)

// ---------------- device scratch (no allocs allowed) ----------------
__device__ float g_part[KS_ * BN_ * GH_];     // gate gemm1 split-K partials
__device__ int   g_gidx[P_ * G_];             // active gene indices per pathway (sorted)
__device__ int   g_gcnt[P_];
__device__ int   g_toff[P_ * (NT_ + 1)];      // per-pathway tile boundaries in g_gidx
__device__ int   g_pl_b[P_ * BN_];            // per-pathway sample lists
__device__ float g_pl_w[P_ * BN_];
__device__ int   g_pl_slot[P_ * BN_];
__device__ int   g_pcnt[P_];
__device__ int   g_done;
__device__ int   g_item_p[MAXITEMS_ + 32];
__device__ int   g_item_c[MAXITEMS_ + 32];
__device__ int   g_nitems;
__device__ float g_hpart[MAXITEMS_ * RS_ * SCH_ * H_];  // expert partial hidden
__device__ float g_contrib[BN_ * K_ * O_];    // per-(sample,slot) expert contribution

__device__ __forceinline__ float neg_inf() { return __int_as_float(0xff800000); }

// ---------------- kernel 1: pre (compaction for bid<128; zero/reset for bid>=128) ----------------
__global__ void __launch_bounds__(256) k_pre(const float* __restrict__ mask,
                                             float* __restrict__ out, int total_out) {
    int bid = blockIdx.x, t = threadIdx.x;
    if (bid >= P_) {
        int i = (bid - P_) * 256 + t;
        if (i < total_out) out[i] = 0.0f;
        if (bid == P_) {
            if (t < P_) g_pcnt[t] = 0;
            if (t == 0) { g_done = 0; g_nitems = 0; }
        }
        return;
    }
    int p = bid;
    __shared__ int wtot[8];
    int lane = t & 31, w = t >> 5;
    int g0 = t * GPB_;
    int c = 0;
    unsigned am = 0;
    #pragma unroll
    for (int i = 0; i < GPB_; i++) {
        int g = g0 + i;
        if (g < G_ && mask[g * P_ + p] > 0.5f) { am |= (1u << i); c++; }
    }
    // block exclusive scan of c
    int inc = c;
    #pragma unroll
    for (int s = 1; s < 32; s <<= 1) {
        int v = __shfl_up_sync(0xffffffffu, inc, s);
        if (lane >= s) inc += v;
    }
    if (lane == 31) wtot[w] = inc;
    __syncthreads();
    int wpre = 0;
    #pragma unroll
    for (int i = 0; i < 8; i++) if (i < w) wpre += wtot[i];
    int off = wpre + inc - c;      // exclusive prefix
    #pragma unroll
    for (int i = 0; i < GPB_; i++)
        if (am & (1u << i)) g_gidx[p * G_ + off++] = g0 + i;
    int cnt = 0;
    #pragma unroll
    for (int i = 0; i < 8; i++) cnt += wtot[i];
    if (t == 0) g_gcnt[p] = cnt;
    __syncthreads();   // g_gidx writes visible block-wide
    if (t <= NT_) {
        int target = t * GT_;
        int lo = 0, hi = cnt;
        while (lo < hi) {
            int mid = (lo + hi) >> 1;
            if (g_gidx[p * G_ + mid] < target) lo = mid + 1; else hi = mid;
        }
        g_toff[p * (NT_ + 1) + t] = lo;
    }
}

// ---------------- kernel 2: gate GEMM1 split-K  C1_part = x_rna @ gate_w1 ----------------
__global__ void k_gemm1(const float* __restrict__ A, const float* __restrict__ Bw) {
    __shared__ __align__(16) float As[KT_][TM_];   // transposed A tile
    __shared__ __align__(16) float Bs[KT_][TN_];
    int m0 = blockIdx.x * TM_;
    int n0 = blockIdx.y * TN_;
    int ks = blockIdx.z;
    int k0 = ks * KCH_;
    int t = threadIdx.x;                 // 256
    int tx = t & 15, ty = t >> 4;        // 16 x 16; thread tile 4 rows x 2 cols
    float acc[4][2];
    #pragma unroll
    for (int i = 0; i < 4; i++) { acc[i][0] = 0.0f; acc[i][1] = 0.0f; }

    for (int kk = 0; kk < KCH_; kk += KT_) {
        #pragma unroll
        for (int i = 0; i < 2; i++) {
            int e = t + i * 256;
            int r = e >> 3, c = e & 7;
            As[c][r] = A[(m0 + r) * G_ + k0 + kk + c];
        }
        {
            int kr = t >> 5, c = t & 31;    // 8 x 32 = 256
            Bs[kr][c] = Bw[(k0 + kk + kr) * GH_ + n0 + c];
        }
        __syncthreads();
        #pragma unroll
        for (int k = 0; k < KT_; k++) {
            float4 a = *(const float4*)&As[k][ty * 4];
            float2 b = *(const float2*)&Bs[k][tx * 2];
            acc[0][0] += a.x * b.x; acc[0][1] += a.x * b.y;
            acc[1][0] += a.y * b.x; acc[1][1] += a.y * b.y;
            acc[2][0] += a.z * b.x; acc[2][1] += a.z * b.y;
            acc[3][0] += a.w * b.x; acc[3][1] += a.w * b.y;
        }
        __syncthreads();
    }
    #pragma unroll
    for (int i = 0; i < 4; i++) {
        float2 v = make_float2(acc[i][0], acc[i][1]);
        *(float2*)&g_part[(ks * BN_ + m0 + ty * 4 + i) * GH_ + n0 + tx * 2] = v;
    }
}

// ---------------- kernel 3: gate (block per sample) + fused planner (last block) ----------------
__global__ void __launch_bounds__(128) k_gate(
    const float* __restrict__ gb1, const float* __restrict__ W2g,
    const float* __restrict__ gb2, float* __restrict__ out_gw) {
    int b = blockIdx.x;
    int t = threadIdx.x;       // 128 : pathway index
    __shared__ float c1s[GH_];
    __shared__ float slog[P_];
    __shared__ int   sc[P_];
    __shared__ int   is_last;

    // split-K reduce + bias + relu (coalesced over t)
    float v = gb1[t];
    #pragma unroll
    for (int ks = 0; ks < KS_; ks++) v += g_part[(ks * BN_ + b) * GH_ + t];
    c1s[t] = fmaxf(v, 0.0f);
    __syncthreads();

    // GEMM2: thread t = pathway t, 4 interleaved accumulators
    float a0 = 0.f, a1 = 0.f, a2 = 0.f, a3 = 0.f;
    #pragma unroll 4
    for (int h = 0; h < GH_; h += 4) {
        a0 += c1s[h + 0] * W2g[(h + 0) * P_ + t];
        a1 += c1s[h + 1] * W2g[(h + 1) * P_ + t];
        a2 += c1s[h + 2] * W2g[(h + 2) * P_ + t];
        a3 += c1s[h + 3] * W2g[(h + 3) * P_ + t];
    }
    slog[t] = gb2[t] + ((a0 + a1) + (a2 + a3));
    __syncthreads();

    // warp 0: top-3 over 128 (4 candidates per lane), ties -> lowest index
    if (t < 32) {
        int lane = t;
        float acc[4]; int idx[4];
        #pragma unroll
        for (int q = 0; q < 4; q++) { acc[q] = slog[q * 32 + lane]; idx[q] = q * 32 + lane; }
        float topv[K_]; int topi[K_];
        #pragma unroll
        for (int k = 0; k < K_; k++) {
            float bv = acc[0]; int bi = idx[0];
            #pragma unroll
            for (int q = 1; q < 4; q++)
                if (acc[q] > bv || (acc[q] == bv && idx[q] < bi)) { bv = acc[q]; bi = idx[q]; }
            #pragma unroll
            for (int s = 16; s > 0; s >>= 1) {
                float ov = __shfl_xor_sync(0xffffffffu, bv, s);
                int   oi = __shfl_xor_sync(0xffffffffu, bi, s);
                if (ov > bv || (ov == bv && oi < bi)) { bv = ov; bi = oi; }
            }
            topv[k] = bv; topi[k] = bi;
            #pragma unroll
            for (int q = 0; q < 4; q++) if (idx[q] == bi) acc[q] = neg_inf();
        }
        if (lane < K_) {
            float gw = 1.0f / (1.0f + expf(-topv[lane]));
            int p = topi[lane];
            out_gw[b * P_ + p] = gw;
            int pos = atomicAdd(&g_pcnt[p], 1);
            g_pl_b[p * BN_ + pos]    = b;
            g_pl_w[p * BN_ + pos]    = gw;
            g_pl_slot[p * BN_ + pos] = lane;
            __threadfence();
        }
    }
    // fused planner: last finished block builds the item list
    __syncthreads();
    if (t == 0) {
        __threadfence();
        int old = atomicAdd(&g_done, 1);
        is_last = (old == BN_ - 1) ? 1 : 0;
    }
    __syncthreads();
    if (is_last) {
        __threadfence();
        int n = atomicAdd(&g_pcnt[t], 0);    // coherent read
        int cch = (n + SCH_ - 1) / SCH_;
        sc[t] = cch;
        __syncthreads();
        for (int d = 1; d < P_; d <<= 1) {
            int vv = (t >= d) ? sc[t - d] : 0;
            __syncthreads();
            sc[t] += vv;
            __syncthreads();
        }
        int off = sc[t] - cch;
        for (int i = 0; i < cch; i++) { g_item_p[off + i] = t; g_item_c[off + i] = i * SCH_; }
        if (t == P_ - 1) g_nitems = sc[t];
    }
}

// ---------------- kernel 4: expert partial (dense staging, H-vectorized FMA) ----------------
__global__ void __launch_bounds__(256) k_expert_part(
    const float* __restrict__ x_rna, const float* __restrict__ x_cnv, const float* __restrict__ x_met,
    const float* __restrict__ W1)
{
    int item = blockIdx.x;
    if (item >= g_nitems) return;
    int rs   = blockIdx.y;               // 0..5 : omic = rs/2, gene half = rs&1
    int o    = rs >> 1;
    int thalf= rs & 1;
    int p    = g_item_p[item];
    int base = g_item_c[item];
    int cnt  = g_pcnt[p];
    int ns   = min(SCH_, max(0, cnt - base));
    if (ns == 0) return;

    int t  = threadIdx.x;          // 256
    int j4 = t & 15;               // h quad: h = j4*4 + hh
    int rg = t >> 4;               // 16 row groups

    // shared overlay: phase A (sX 24000B + sg 2000B) / phase B (red 32768B)
    __shared__ __align__(16) unsigned char sraw[32768];
    float (*sX)[XSTR_] = (float(*)[XSTR_])sraw;                 // [GT_][12]
    int*   sg          = (int*)(sraw + GT_ * XSTR_ * 4);        // [GT_]
    float (*red)[SCH_][H_] = (float(*)[SCH_][H_])sraw;          // [16][8][64]
    __shared__ int sb[SCH_];

    if (t < SCH_) sb[t] = (t < ns) ? g_pl_b[p * BN_ + base + t] : 0;
    __syncthreads();

    const float* xo  = (o == 0) ? x_rna : ((o == 1) ? x_cnv : x_met);
    const float* w1p = W1 + (long)p * (D_ * H_) + (long)o * (G_ * H_);
    const int* toff = &g_toff[p * (NT_ + 1)];

    float acc[4][SCH_];
    #pragma unroll
    for (int hh = 0; hh < 4; hh++)
        #pragma unroll
        for (int s = 0; s < SCH_; s++) acc[hh][s] = 0.0f;

    for (int tt = thalf * 4; tt < thalf * 4 + 4; tt++) {
        int g0 = tt * GT_;
        int seg0 = toff[tt], seg1 = toff[tt + 1];
        int nact = seg1 - seg0;
        // stage dense x slab, gene-major: coalesced gmem reads over g
        for (int e = t; e < GT_ * SCH_; e += 256) {
            int s = e / GT_;
            int g = e - s * GT_;
            sX[g][s] = (s < ns) ? xo[sb[s] * G_ + g0 + g] : 0.0f;
        }
        for (int e = t; e < nact; e += 256) sg[e] = g_gidx[p * G_ + seg0 + e] - g0;
        __syncthreads();
        // compute: per row = 1 LDG.128 (W1 quad) + 2 LDS.128 (x8) + 32 FFMA
        #pragma unroll 2
        for (int r = rg; r < nact; r += 16) {
            int gl = sg[r];
            float4 w4 = *(const float4*)&w1p[(long)(g0 + gl) * H_ + j4 * 4];
            float4 xa = *(const float4*)&sX[gl][0];
            float4 xb = *(const float4*)&sX[gl][4];
            acc[0][0] += w4.x * xa.x; acc[0][1] += w4.x * xa.y; acc[0][2] += w4.x * xa.z; acc[0][3] += w4.x * xa.w;
            acc[0][4] += w4.x * xb.x; acc[0][5] += w4.x * xb.y; acc[0][6] += w4.x * xb.z; acc[0][7] += w4.x * xb.w;
            acc[1][0] += w4.y * xa.x; acc[1][1] += w4.y * xa.y; acc[1][2] += w4.y * xa.z; acc[1][3] += w4.y * xa.w;
            acc[1][4] += w4.y * xb.x; acc[1][5] += w4.y * xb.y; acc[1][6] += w4.y * xb.z; acc[1][7] += w4.y * xb.w;
            acc[2][0] += w4.z * xa.x; acc[2][1] += w4.z * xa.y; acc[2][2] += w4.z * xa.z; acc[2][3] += w4.z * xa.w;
            acc[2][4] += w4.z * xb.x; acc[2][5] += w4.z * xb.y; acc[2][6] += w4.z * xb.z; acc[2][7] += w4.z * xb.w;
            acc[3][0] += w4.w * xa.x; acc[3][1] += w4.w * xa.y; acc[3][2] += w4.w * xa.z; acc[3][3] += w4.w * xa.w;
            acc[3][4] += w4.w * xb.x; acc[3][5] += w4.w * xb.y; acc[3][6] += w4.w * xb.z; acc[3][7] += w4.w * xb.w;
        }
        __syncthreads();
    }

    // phase B: red aliases sX (all compute done after final sync above)
    #pragma unroll
    for (int hh = 0; hh < 4; hh++)
        #pragma unroll
        for (int s = 0; s < SCH_; s++)
            red[rg][s][j4 * 4 + hh] = acc[hh][s];
    __syncthreads();

    for (int u = t; u < SCH_ * H_; u += 256) {
        int s = u >> 6, h = u & 63;
        float sum = 0.0f;
        #pragma unroll
        for (int g = 0; g < 16; g++) sum += red[g][s][h];
        g_hpart[((item * RS_ + rs) * SCH_ + s) * H_ + h] = sum;
    }
}

// ---------------- kernel 5: expert finish: reduce splits + BN + ReLU + W2 ----------------
__global__ void __launch_bounds__(128) k_expert_fin(
    const float* __restrict__ eb1,
    const float* __restrict__ gamma, const float* __restrict__ beta,
    const float* __restrict__ mean,  const float* __restrict__ var,
    const float* __restrict__ W2,    const float* __restrict__ eb2)
{
    int item = blockIdx.x;
    if (item >= g_nitems) return;
    int p    = g_item_p[item];
    int base = g_item_c[item];
    int cnt  = g_pcnt[p];
    int ns   = min(SCH_, max(0, cnt - base));
    if (ns == 0) return;

    int t = threadIdx.x;   // 128
    __shared__ int   sb[SCH_];
    __shared__ float swt[SCH_];
    __shared__ int   sslot[SCH_];
    __shared__ float hsh[SCH_][H_];

    if (t < SCH_ && t < ns) {
        sb[t]    = g_pl_b[p * BN_ + base + t];
        swt[t]   = g_pl_w[p * BN_ + base + t];
        sslot[t] = g_pl_slot[p * BN_ + base + t];
    }
    __syncthreads();

    if (t < H_) {
        float b1v = eb1[p * H_ + t];
        float mn  = mean[p * H_ + t];
        float sc  = gamma[p * H_ + t] * rsqrtf(var[p * H_ + t] + EPS_);
        float bt  = beta[p * H_ + t];
        #pragma unroll
        for (int s = 0; s < SCH_; s++) {
            float hv = b1v;
            #pragma unroll
            for (int rs = 0; rs < RS_; rs++)
                hv += g_hpart[((item * RS_ + rs) * SCH_ + s) * H_ + t];
            hv = (hv - mn) * sc + bt;
            hsh[s][t] = fmaxf(hv, 0.0f);
        }
    }
    __syncthreads();

    if (t < SCH_ * O_) {
        int s = t >> 4, o = t & 15;
        if (s < ns) {
            float a = eb2[p * O_ + o];
            #pragma unroll 8
            for (int jj = 0; jj < H_; jj++) a += hsh[s][jj] * W2[(p * H_ + jj) * O_ + o];
            g_contrib[(sb[s] * K_ + sslot[s]) * O_ + o] = swt[s] * a;
        }
    }
}

// ---------------- kernel 6: feat sum + classifier ----------------
__global__ void k_final(const float* __restrict__ cw1, const float* __restrict__ cb1,
                        const float* __restrict__ cw2, const float* __restrict__ cb2,
                        float* __restrict__ out_logits) {
    int b = threadIdx.x;   // 256
    float f[O_];
    #pragma unroll
    for (int o = 0; o < O_; o++)
        f[o] = g_contrib[(b * K_ + 0) * O_ + o]
             + g_contrib[(b * K_ + 1) * O_ + o]
             + g_contrib[(b * K_ + 2) * O_ + o];
    float hc[CH_];
    #pragma unroll
    for (int c = 0; c < CH_; c++) {
        float a = cb1[c];
        #pragma unroll
        for (int o = 0; o < O_; o++) a += f[o] * cw1[o * CH_ + c];
        hc[c] = fmaxf(a, 0.0f);
    }
    #pragma unroll
    for (int c = 0; c < C_; c++) {
        float a = cb2[c];
        #pragma unroll
        for (int h = 0; h < CH_; h++) a += hc[h] * cw2[h * C_ + c];
        out_logits[b * C_ + c] = a;
    }
}

// ---------------- launch ----------------
extern "C" void kernel_launch(void* const* d_in, const int* in_sizes, int n_in,
                              void* d_out, int out_size) {
    const float* x_rna     = (const float*)d_in[0];
    const float* x_cnv     = (const float*)d_in[1];
    const float* x_met     = (const float*)d_in[2];
    const float* gene_mask = (const float*)d_in[3];
    const float* gate_w1   = (const float*)d_in[4];
    const float* gate_b1   = (const float*)d_in[5];
    const float* gate_w2   = (const float*)d_in[6];
    const float* gate_b2   = (const float*)d_in[7];
    const float* W1        = (const float*)d_in[8];
    const float* eb1       = (const float*)d_in[9];
    const float* bn_gamma  = (const float*)d_in[10];
    const float* bn_beta   = (const float*)d_in[11];
    const float* bn_mean   = (const float*)d_in[12];
    const float* bn_var    = (const float*)d_in[13];
    const float* W2        = (const float*)d_in[14];
    const float* eb2       = (const float*)d_in[15];
    const float* cls_w1    = (const float*)d_in[16];
    const float* cls_b1    = (const float*)d_in[17];
    const float* cls_w2    = (const float*)d_in[18];
    const float* cls_b2    = (const float*)d_in[19];

    float* out        = (float*)d_out;
    float* out_logits = out;             // [B, C] first (tuple order)
    float* out_gw     = out + BN_ * C_;  // [B, P]

    int total_out = BN_ * C_ + BN_ * P_;
    if (total_out > out_size) total_out = out_size;
    int zb = (total_out + 255) / 256;

    k_pre<<<P_ + zb, 256>>>(gene_mask, out, total_out);                 // 1
    dim3 g1(BN_ / TM_, GH_ / TN_, KS_);
    k_gemm1<<<g1, 256>>>(x_rna, gate_w1);                               // 2
    k_gate<<<BN_, 128>>>(gate_b1, gate_w2, gate_b2, out_gw);            // 3
    dim3 ge(MAXITEMS_, RS_);
    k_expert_part<<<ge, 256>>>(x_rna, x_cnv, x_met, W1);                // 4  <- profiled slot
    k_expert_fin<<<MAXITEMS_, 128>>>(eb1, bn_gamma, bn_beta, bn_mean, bn_var, W2, eb2);  // 5
    k_final<<<1, 256>>>(cls_w1, cls_b1, cls_w2, cls_b2, out_logits);    // 6
}

// round 7
// speedup vs baseline: 1.0752x; 1.0752x over previous
#include <cuda_runtime.h>
#include <math.h>

#define BN_ 256      // batch
#define G_  4000     // genes
#define P_  128      // pathways
#define D_  12000    // expert in dim
#define H_  64       // expert hidden
#define O_  16       // expert out
#define GH_ 128      // gate hidden
#define CH_ 8        // classifier hidden
#define C_  5        // classes
#define K_  3        // top_k
#define EPS_ 1e-5f

// ---- gate GEMM1 config ----
#define KS_  20      // K splits
#define KCH_ 200     // 4000 / 20
#define TM_  64
#define TN_  32
#define KT_  8

// ---- expert config ----
#define SCH_ 8       // samples per chunk
#define RS_  6       // row splits per item
#define R3MAX_ 2400  // max rows per pathway (3 * NGMAX, NGMAX=800 >> max ~470)
#define SPLITMAX_ 400   // ceil(R3MAX_/RS_)
#define MAXITEMS_ 224
#define GCH_ 75      // gather chunks per item: 2400*8/256

// ---- compaction ----
#define GPB_ 16      // genes owned per thread (256*16 = 4096 >= 4000)

// ---------------- device scratch (no allocs allowed) ----------------
__device__ float g_part[KS_ * BN_ * GH_];     // gate gemm1 split-K partials
__device__ int   g_gidx[P_ * G_];             // active gene indices per pathway (sorted)
__device__ int   g_gcnt[P_];
__device__ int   g_rowd[P_ * D_];             // per-pathway row -> d (= o*G + g)
__device__ int   g_pl_b[P_ * BN_];            // per-pathway sample lists
__device__ float g_pl_w[P_ * BN_];
__device__ int   g_pl_slot[P_ * BN_];
__device__ int   g_pcnt[P_];
__device__ int   g_done;
__device__ int   g_item_p[MAXITEMS_ + 32];
__device__ int   g_item_c[MAXITEMS_ + 32];
__device__ int   g_nitems;
__device__ float g_xg[(long)MAXITEMS_ * R3MAX_ * SCH_];  // gathered x, [item][row][s]
__device__ float g_hpart[MAXITEMS_ * RS_ * SCH_ * H_];   // expert partial hidden
__device__ float g_contrib[BN_ * K_ * O_];    // per-(sample,slot) expert contribution

__device__ __forceinline__ float neg_inf() { return __int_as_float(0xff800000); }

// ---------------- kernel 1: pre (compaction + rowd for bid<128; zero/reset else) ----------------
__global__ void __launch_bounds__(256) k_pre(const float* __restrict__ mask,
                                             float* __restrict__ out, int total_out) {
    int bid = blockIdx.x, t = threadIdx.x;
    if (bid >= P_) {
        int i = (bid - P_) * 256 + t;
        if (i < total_out) out[i] = 0.0f;
        if (bid == P_) {
            if (t < P_) g_pcnt[t] = 0;
            if (t == 0) { g_done = 0; g_nitems = 0; }
        }
        return;
    }
    int p = bid;
    __shared__ int wtot[8];
    int lane = t & 31, w = t >> 5;
    int g0 = t * GPB_;
    int c = 0;
    unsigned am = 0;
    #pragma unroll
    for (int i = 0; i < GPB_; i++) {
        int g = g0 + i;
        if (g < G_ && mask[g * P_ + p] > 0.5f) { am |= (1u << i); c++; }
    }
    // block exclusive scan of c
    int inc = c;
    #pragma unroll
    for (int s = 1; s < 32; s <<= 1) {
        int v = __shfl_up_sync(0xffffffffu, inc, s);
        if (lane >= s) inc += v;
    }
    if (lane == 31) wtot[w] = inc;
    __syncthreads();
    int wpre = 0;
    #pragma unroll
    for (int i = 0; i < 8; i++) if (i < w) wpre += wtot[i];
    int off = wpre + inc - c;      // exclusive prefix
    #pragma unroll
    for (int i = 0; i < GPB_; i++)
        if (am & (1u << i)) g_gidx[p * G_ + off++] = g0 + i;
    int cnt = 0;
    #pragma unroll
    for (int i = 0; i < 8; i++) cnt += wtot[i];
    if (t == 0) g_gcnt[p] = cnt;
    __syncthreads();   // g_gidx writes visible block-wide
    // row -> d table (rows: 3 omics x cnt genes)
    int R = 3 * cnt;
    for (int r = t; r < R; r += 256) {
        int o = (r >= cnt) + (r >= 2 * cnt);
        int g = g_gidx[p * G_ + r - o * cnt];
        g_rowd[p * D_ + r] = o * G_ + g;
    }
}

// ---------------- kernel 2: gate GEMM1 split-K  C1_part = x_rna @ gate_w1 ----------------
__global__ void k_gemm1(const float* __restrict__ A, const float* __restrict__ Bw) {
    __shared__ __align__(16) float As[KT_][TM_];   // transposed A tile
    __shared__ __align__(16) float Bs[KT_][TN_];
    int m0 = blockIdx.x * TM_;
    int n0 = blockIdx.y * TN_;
    int ks = blockIdx.z;
    int k0 = ks * KCH_;
    int t = threadIdx.x;                 // 256
    int tx = t & 15, ty = t >> 4;        // 16 x 16; thread tile 4 rows x 2 cols
    float acc[4][2];
    #pragma unroll
    for (int i = 0; i < 4; i++) { acc[i][0] = 0.0f; acc[i][1] = 0.0f; }

    for (int kk = 0; kk < KCH_; kk += KT_) {
        #pragma unroll
        for (int i = 0; i < 2; i++) {
            int e = t + i * 256;
            int r = e >> 3, c = e & 7;
            As[c][r] = A[(m0 + r) * G_ + k0 + kk + c];
        }
        {
            int kr = t >> 5, c = t & 31;    // 8 x 32 = 256
            Bs[kr][c] = Bw[(k0 + kk + kr) * GH_ + n0 + c];
        }
        __syncthreads();
        #pragma unroll
        for (int k = 0; k < KT_; k++) {
            float4 a = *(const float4*)&As[k][ty * 4];
            float2 b = *(const float2*)&Bs[k][tx * 2];
            acc[0][0] += a.x * b.x; acc[0][1] += a.x * b.y;
            acc[1][0] += a.y * b.x; acc[1][1] += a.y * b.y;
            acc[2][0] += a.z * b.x; acc[2][1] += a.z * b.y;
            acc[3][0] += a.w * b.x; acc[3][1] += a.w * b.y;
        }
        __syncthreads();
    }
    #pragma unroll
    for (int i = 0; i < 4; i++) {
        float2 v = make_float2(acc[i][0], acc[i][1]);
        *(float2*)&g_part[(ks * BN_ + m0 + ty * 4 + i) * GH_ + n0 + tx * 2] = v;
    }
}

// ---------------- kernel 3: gate (block per sample) + fused planner (last block) ----------------
__global__ void __launch_bounds__(128) k_gate(
    const float* __restrict__ gb1, const float* __restrict__ W2g,
    const float* __restrict__ gb2, float* __restrict__ out_gw) {
    int b = blockIdx.x;
    int t = threadIdx.x;       // 128 : pathway index
    __shared__ float c1s[GH_];
    __shared__ float slog[P_];
    __shared__ int   sc[P_];
    __shared__ int   is_last;

    // split-K reduce + bias + relu (coalesced over t)
    float v = gb1[t];
    #pragma unroll
    for (int ks = 0; ks < KS_; ks++) v += g_part[(ks * BN_ + b) * GH_ + t];
    c1s[t] = fmaxf(v, 0.0f);
    __syncthreads();

    // GEMM2: thread t = pathway t, 4 interleaved accumulators
    float a0 = 0.f, a1 = 0.f, a2 = 0.f, a3 = 0.f;
    #pragma unroll 4
    for (int h = 0; h < GH_; h += 4) {
        a0 += c1s[h + 0] * W2g[(h + 0) * P_ + t];
        a1 += c1s[h + 1] * W2g[(h + 1) * P_ + t];
        a2 += c1s[h + 2] * W2g[(h + 2) * P_ + t];
        a3 += c1s[h + 3] * W2g[(h + 3) * P_ + t];
    }
    slog[t] = gb2[t] + ((a0 + a1) + (a2 + a3));
    __syncthreads();

    // warp 0: top-3 over 128 (4 candidates per lane), ties -> lowest index
    if (t < 32) {
        int lane = t;
        float acc[4]; int idx[4];
        #pragma unroll
        for (int q = 0; q < 4; q++) { acc[q] = slog[q * 32 + lane]; idx[q] = q * 32 + lane; }
        float topv[K_]; int topi[K_];
        #pragma unroll
        for (int k = 0; k < K_; k++) {
            float bv = acc[0]; int bi = idx[0];
            #pragma unroll
            for (int q = 1; q < 4; q++)
                if (acc[q] > bv || (acc[q] == bv && idx[q] < bi)) { bv = acc[q]; bi = idx[q]; }
            #pragma unroll
            for (int s = 16; s > 0; s >>= 1) {
                float ov = __shfl_xor_sync(0xffffffffu, bv, s);
                int   oi = __shfl_xor_sync(0xffffffffu, bi, s);
                if (ov > bv || (ov == bv && oi < bi)) { bv = ov; bi = oi; }
            }
            topv[k] = bv; topi[k] = bi;
            #pragma unroll
            for (int q = 0; q < 4; q++) if (idx[q] == bi) acc[q] = neg_inf();
        }
        if (lane < K_) {
            float gw = 1.0f / (1.0f + expf(-topv[lane]));
            int p = topi[lane];
            out_gw[b * P_ + p] = gw;
            int pos = atomicAdd(&g_pcnt[p], 1);
            g_pl_b[p * BN_ + pos]    = b;
            g_pl_w[p * BN_ + pos]    = gw;
            g_pl_slot[p * BN_ + pos] = lane;
            __threadfence();
        }
    }
    // fused planner: last finished block builds the item list
    __syncthreads();
    if (t == 0) {
        __threadfence();
        int old = atomicAdd(&g_done, 1);
        is_last = (old == BN_ - 1) ? 1 : 0;
    }
    __syncthreads();
    if (is_last) {
        __threadfence();
        int n = atomicAdd(&g_pcnt[t], 0);    // coherent read
        int cch = (n + SCH_ - 1) / SCH_;
        sc[t] = cch;
        __syncthreads();
        for (int d = 1; d < P_; d <<= 1) {
            int vv = (t >= d) ? sc[t - d] : 0;
            __syncthreads();
            sc[t] += vv;
            __syncthreads();
        }
        int off = sc[t] - cch;
        for (int i = 0; i < cch; i++) { g_item_p[off + i] = t; g_item_c[off + i] = i * SCH_; }
        if (t == P_ - 1) g_nitems = sc[t];
    }
}

// ---------------- kernel 4: gather x into dense per-item layout ----------------
__global__ void __launch_bounds__(256) k_gather(
    const float* __restrict__ xr, const float* __restrict__ xc, const float* __restrict__ xm) {
    int item = blockIdx.x;
    if (item >= g_nitems) return;
    int p    = g_item_p[item];
    int base = g_item_c[item];
    int cnt  = g_pcnt[p];
    int ns   = min(SCH_, max(0, cnt - base));
    int R    = min(3 * g_gcnt[p], R3MAX_);

    int e = blockIdx.y * 256 + threadIdx.x;
    int r = e >> 3, s = e & 7;
    if (r >= R) return;
    float v = 0.0f;
    if (s < ns) {
        int b = g_pl_b[p * BN_ + base + s];
        int d = g_rowd[p * D_ + r];
        int o = (d >= G_) + (d >= 2 * G_);
        const float* xo = (o == 0) ? xr : ((o == 1) ? xc : xm);
        v = xo[b * G_ + d - o * G_];
    }
    g_xg[((long)item * R3MAX_ + r) * SCH_ + s] = v;
}

// ---------------- kernel 5: expert partial (streaming FMA, no staging) ----------------
__global__ void __launch_bounds__(256) k_expert_part(const float* __restrict__ W1)
{
    int item = blockIdx.x;
    if (item >= g_nitems) return;
    int rs   = blockIdx.y;               // 0..5
    int p    = g_item_p[item];
    int R    = min(3 * g_gcnt[p], R3MAX_);
    int chunk = (R + RS_ - 1) / RS_;
    int r0 = rs * chunk;
    int r1 = min(R, r0 + chunk);
    int n  = r1 - r0;

    int t  = threadIdx.x;          // 256
    int j2 = t & 31;               // h pair: h = j2*2 + {0,1}
    int rg = t >> 5;               // 8 row groups

    __shared__ int   sd[SPLITMAX_];
    __shared__ float red[8][SCH_][H_];   // 16 KB

    if (n <= 0) {                        // must still clear stale partials
        for (int u = t; u < SCH_ * H_; u += 256) {
            int s = u >> 6, h = u & 63;
            g_hpart[((item * RS_ + rs) * SCH_ + s) * H_ + h] = 0.0f;
        }
        return;
    }

    for (int i = t; i < n; i += 256) sd[i] = g_rowd[p * D_ + r0 + i];
    __syncthreads();

    float acc[2][SCH_];
    #pragma unroll
    for (int hh = 0; hh < 2; hh++)
        #pragma unroll
        for (int s = 0; s < SCH_; s++) acc[hh][s] = 0.0f;

    const float* w1p = W1 + (long)p * (D_ * H_);
    const float* xg  = g_xg + (long)item * R3MAX_ * SCH_;

    int i = rg;
    for (; i + 8 < n; i += 16) {
        int d0 = sd[i], d1 = sd[i + 8];
        float2 w0 = *(const float2*)&w1p[(long)d0 * H_ + j2 * 2];
        float2 w1 = *(const float2*)&w1p[(long)d1 * H_ + j2 * 2];
        float4 xa0 = *(const float4*)&xg[(r0 + i) * SCH_];
        float4 xb0 = *(const float4*)&xg[(r0 + i) * SCH_ + 4];
        float4 xa1 = *(const float4*)&xg[(r0 + i + 8) * SCH_];
        float4 xb1 = *(const float4*)&xg[(r0 + i + 8) * SCH_ + 4];
        acc[0][0] += w0.x * xa0.x; acc[0][1] += w0.x * xa0.y; acc[0][2] += w0.x * xa0.z; acc[0][3] += w0.x * xa0.w;
        acc[0][4] += w0.x * xb0.x; acc[0][5] += w0.x * xb0.y; acc[0][6] += w0.x * xb0.z; acc[0][7] += w0.x * xb0.w;
        acc[1][0] += w0.y * xa0.x; acc[1][1] += w0.y * xa0.y; acc[1][2] += w0.y * xa0.z; acc[1][3] += w0.y * xa0.w;
        acc[1][4] += w0.y * xb0.x; acc[1][5] += w0.y * xb0.y; acc[1][6] += w0.y * xb0.z; acc[1][7] += w0.y * xb0.w;
        acc[0][0] += w1.x * xa1.x; acc[0][1] += w1.x * xa1.y; acc[0][2] += w1.x * xa1.z; acc[0][3] += w1.x * xa1.w;
        acc[0][4] += w1.x * xb1.x; acc[0][5] += w1.x * xb1.y; acc[0][6] += w1.x * xb1.z; acc[0][7] += w1.x * xb1.w;
        acc[1][0] += w1.y * xa1.x; acc[1][1] += w1.y * xa1.y; acc[1][2] += w1.y * xa1.z; acc[1][3] += w1.y * xa1.w;
        acc[1][4] += w1.y * xb1.x; acc[1][5] += w1.y * xb1.y; acc[1][6] += w1.y * xb1.z; acc[1][7] += w1.y * xb1.w;
    }
    for (; i < n; i += 8) {
        int d0 = sd[i];
        float2 w0 = *(const float2*)&w1p[(long)d0 * H_ + j2 * 2];
        float4 xa0 = *(const float4*)&xg[(r0 + i) * SCH_];
        float4 xb0 = *(const float4*)&xg[(r0 + i) * SCH_ + 4];
        acc[0][0] += w0.x * xa0.x; acc[0][1] += w0.x * xa0.y; acc[0][2] += w0.x * xa0.z; acc[0][3] += w0.x * xa0.w;
        acc[0][4] += w0.x * xb0.x; acc[0][5] += w0.x * xb0.y; acc[0][6] += w0.x * xb0.z; acc[0][7] += w0.x * xb0.w;
        acc[1][0] += w0.y * xa0.x; acc[1][1] += w0.y * xa0.y; acc[1][2] += w0.y * xa0.z; acc[1][3] += w0.y * xa0.w;
        acc[1][4] += w0.y * xb0.x; acc[1][5] += w0.y * xb0.y; acc[1][6] += w0.y * xb0.z; acc[1][7] += w0.y * xb0.w;
    }

    #pragma unroll
    for (int s = 0; s < SCH_; s++) {
        red[rg][s][j2 * 2 + 0] = acc[0][s];
        red[rg][s][j2 * 2 + 1] = acc[1][s];
    }
    __syncthreads();

    for (int u = t; u < SCH_ * H_; u += 256) {
        int s = u >> 6, h = u & 63;
        float sum = 0.0f;
        #pragma unroll
        for (int g = 0; g < 8; g++) sum += red[g][s][h];
        g_hpart[((item * RS_ + rs) * SCH_ + s) * H_ + h] = sum;
    }
}

// ---------------- kernel 6: expert finish: reduce splits + BN + ReLU + W2 ----------------
__global__ void __launch_bounds__(128) k_expert_fin(
    const float* __restrict__ eb1,
    const float* __restrict__ gamma, const float* __restrict__ beta,
    const float* __restrict__ mean,  const float* __restrict__ var,
    const float* __restrict__ W2,    const float* __restrict__ eb2)
{
    int item = blockIdx.x;
    if (item >= g_nitems) return;
    int p    = g_item_p[item];
    int base = g_item_c[item];
    int cnt  = g_pcnt[p];
    int ns   = min(SCH_, max(0, cnt - base));
    if (ns == 0) return;

    int t = threadIdx.x;   // 128
    __shared__ int   sb[SCH_];
    __shared__ float swt[SCH_];
    __shared__ int   sslot[SCH_];
    __shared__ float hsh[SCH_][H_];

    if (t < SCH_ && t < ns) {
        sb[t]    = g_pl_b[p * BN_ + base + t];
        swt[t]   = g_pl_w[p * BN_ + base + t];
        sslot[t] = g_pl_slot[p * BN_ + base + t];
    }
    __syncthreads();

    if (t < H_) {
        float b1v = eb1[p * H_ + t];
        float mn  = mean[p * H_ + t];
        float sc  = gamma[p * H_ + t] * rsqrtf(var[p * H_ + t] + EPS_);
        float bt  = beta[p * H_ + t];
        #pragma unroll
        for (int s = 0; s < SCH_; s++) {
            float hv = b1v;
            #pragma unroll
            for (int rs = 0; rs < RS_; rs++)
                hv += g_hpart[((item * RS_ + rs) * SCH_ + s) * H_ + t];
            hv = (hv - mn) * sc + bt;
            hsh[s][t] = fmaxf(hv, 0.0f);
        }
    }
    __syncthreads();

    if (t < SCH_ * O_) {
        int s = t >> 4, o = t & 15;
        if (s < ns) {
            float a = eb2[p * O_ + o];
            #pragma unroll 8
            for (int jj = 0; jj < H_; jj++) a += hsh[s][jj] * W2[(p * H_ + jj) * O_ + o];
            g_contrib[(sb[s] * K_ + sslot[s]) * O_ + o] = swt[s] * a;
        }
    }
}

// ---------------- kernel 7: feat sum + classifier ----------------
__global__ void k_final(const float* __restrict__ cw1, const float* __restrict__ cb1,
                        const float* __restrict__ cw2, const float* __restrict__ cb2,
                        float* __restrict__ out_logits) {
    int b = threadIdx.x;   // 256
    float f[O_];
    #pragma unroll
    for (int o = 0; o < O_; o++)
        f[o] = g_contrib[(b * K_ + 0) * O_ + o]
             + g_contrib[(b * K_ + 1) * O_ + o]
             + g_contrib[(b * K_ + 2) * O_ + o];
    float hc[CH_];
    #pragma unroll
    for (int c = 0; c < CH_; c++) {
        float a = cb1[c];
        #pragma unroll
        for (int o = 0; o < O_; o++) a += f[o] * cw1[o * CH_ + c];
        hc[c] = fmaxf(a, 0.0f);
    }
    #pragma unroll
    for (int c = 0; c < C_; c++) {
        float a = cb2[c];
        #pragma unroll
        for (int h = 0; h < CH_; h++) a += hc[h] * cw2[h * C_ + c];
        out_logits[b * C_ + c] = a;
    }
}

// ---------------- launch ----------------
extern "C" void kernel_launch(void* const* d_in, const int* in_sizes, int n_in,
                              void* d_out, int out_size) {
    const float* x_rna     = (const float*)d_in[0];
    const float* x_cnv     = (const float*)d_in[1];
    const float* x_met     = (const float*)d_in[2];
    const float* gene_mask = (const float*)d_in[3];
    const float* gate_w1   = (const float*)d_in[4];
    const float* gate_b1   = (const float*)d_in[5];
    const float* gate_w2   = (const float*)d_in[6];
    const float* gate_b2   = (const float*)d_in[7];
    const float* W1        = (const float*)d_in[8];
    const float* eb1       = (const float*)d_in[9];
    const float* bn_gamma  = (const float*)d_in[10];
    const float* bn_beta   = (const float*)d_in[11];
    const float* bn_mean   = (const float*)d_in[12];
    const float* bn_var    = (const float*)d_in[13];
    const float* W2        = (const float*)d_in[14];
    const float* eb2       = (const float*)d_in[15];
    const float* cls_w1    = (const float*)d_in[16];
    const float* cls_b1    = (const float*)d_in[17];
    const float* cls_w2    = (const float*)d_in[18];
    const float* cls_b2    = (const float*)d_in[19];

    float* out        = (float*)d_out;
    float* out_logits = out;             // [B, C] first (tuple order)
    float* out_gw     = out + BN_ * C_;  // [B, P]

    int total_out = BN_ * C_ + BN_ * P_;
    if (total_out > out_size) total_out = out_size;
    int zb = (total_out + 255) / 256;

    k_pre<<<P_ + zb, 256>>>(gene_mask, out, total_out);                 // 1
    dim3 g1(BN_ / TM_, GH_ / TN_, KS_);
    k_gemm1<<<g1, 256>>>(x_rna, gate_w1);                               // 2
    k_gate<<<BN_, 128>>>(gate_b1, gate_w2, gate_b2, out_gw);            // 3
    dim3 gg(MAXITEMS_, GCH_);
    k_gather<<<gg, 256>>>(x_rna, x_cnv, x_met);                         // 4  <- profiled slot
    dim3 ge(MAXITEMS_, RS_);
    k_expert_part<<<ge, 256>>>(W1);                                     // 5
    k_expert_fin<<<MAXITEMS_, 128>>>(eb1, bn_gamma, bn_beta, bn_mean, bn_var, W2, eb2);  // 6
    k_final<<<1, 256>>>(cls_w1, cls_b1, cls_w2, cls_b2, out_logits);    // 7
}

// round 8
// speedup vs baseline: 1.3592x; 1.2641x over previous
#include <cuda_runtime.h>
#include <math.h>

#define BN_ 256      // batch
#define G_  4000     // genes
#define P_  128      // pathways
#define D_  12000    // expert in dim
#define H_  64       // expert hidden
#define O_  16       // expert out
#define GH_ 128      // gate hidden
#define CH_ 8        // classifier hidden
#define C_  5        // classes
#define K_  3        // top_k
#define EPS_ 1e-5f

// ---- gate GEMM1 config ----
#define KS_  20      // K splits
#define KCH_ 200     // 4000 / 20
#define TM_  64
#define TN_  32
#define KT_  8

// ---- expert config ----
#define SCH_ 8       // samples per chunk
#define RS_  6       // row splits per item
#define R3MAX_ 2400  // max rows per pathway (3 * 800 >> actual ~1300)
#define SPLITMAX_ 400   // ceil(R3MAX_/RS_)
#define MAXITEMS_ 224

// ---- compaction ----
#define GPB_ 16      // genes owned per thread (256*16 = 4096 >= 4000)

// ---------------- device scratch (no allocs allowed) ----------------
__device__ float g_part[KS_ * BN_ * GH_];     // gate gemm1 split-K partials
__device__ int   g_gidx[P_ * G_];             // active gene indices per pathway (sorted)
__device__ int   g_gcnt[P_];
__device__ int   g_rowd[P_ * D_];             // per-pathway row -> d (= o*G + g)
__device__ int   g_pl_b[P_ * BN_];            // per-pathway sample lists
__device__ float g_pl_w[P_ * BN_];
__device__ int   g_pl_slot[P_ * BN_];
__device__ int   g_pcnt[P_];
__device__ int   g_done;
__device__ int   g_done2;
__device__ int   g_item_p[MAXITEMS_ + 32];
__device__ int   g_item_c[MAXITEMS_ + 32];
__device__ int   g_nitems;
__device__ float g_hpart[MAXITEMS_ * RS_ * SCH_ * H_];   // expert partial hidden
__device__ float g_contrib[BN_ * K_ * O_];    // per-(sample,slot) expert contribution

__device__ __forceinline__ float neg_inf() { return __int_as_float(0xff800000); }

// ---------------- kernel 1: pre (compaction + rowd for bid<128; zero/reset else) ----------------
__global__ void __launch_bounds__(256) k_pre(const float* __restrict__ mask,
                                             float* __restrict__ out, int total_out) {
    int bid = blockIdx.x, t = threadIdx.x;
    if (bid >= P_) {
        int i = (bid - P_) * 256 + t;
        if (i < total_out) out[i] = 0.0f;
        if (bid == P_) {
            if (t < P_) g_pcnt[t] = 0;
            if (t == 0) { g_done = 0; g_done2 = 0; g_nitems = 0; }
        }
        return;
    }
    int p = bid;
    __shared__ int wtot[8];
    int lane = t & 31, w = t >> 5;
    int g0 = t * GPB_;
    int c = 0;
    unsigned am = 0;
    #pragma unroll
    for (int i = 0; i < GPB_; i++) {
        int g = g0 + i;
        if (g < G_ && mask[g * P_ + p] > 0.5f) { am |= (1u << i); c++; }
    }
    // block exclusive scan of c
    int inc = c;
    #pragma unroll
    for (int s = 1; s < 32; s <<= 1) {
        int v = __shfl_up_sync(0xffffffffu, inc, s);
        if (lane >= s) inc += v;
    }
    if (lane == 31) wtot[w] = inc;
    __syncthreads();
    int wpre = 0;
    #pragma unroll
    for (int i = 0; i < 8; i++) if (i < w) wpre += wtot[i];
    int off = wpre + inc - c;      // exclusive prefix
    #pragma unroll
    for (int i = 0; i < GPB_; i++)
        if (am & (1u << i)) g_gidx[p * G_ + off++] = g0 + i;
    int cnt = 0;
    #pragma unroll
    for (int i = 0; i < 8; i++) cnt += wtot[i];
    if (t == 0) g_gcnt[p] = cnt;
    __syncthreads();   // g_gidx writes visible block-wide
    // row -> d table (rows: 3 omics x cnt genes)
    int R = 3 * cnt;
    for (int r = t; r < R; r += 256) {
        int o = (r >= cnt) + (r >= 2 * cnt);
        int g = g_gidx[p * G_ + r - o * cnt];
        g_rowd[p * D_ + r] = o * G_ + g;
    }
}

// ---------------- kernel 2: gate GEMM1 split-K  C1_part = x_rna @ gate_w1 ----------------
__global__ void k_gemm1(const float* __restrict__ A, const float* __restrict__ Bw) {
    __shared__ __align__(16) float As[KT_][TM_];   // transposed A tile
    __shared__ __align__(16) float Bs[KT_][TN_];
    int m0 = blockIdx.x * TM_;
    int n0 = blockIdx.y * TN_;
    int ks = blockIdx.z;
    int k0 = ks * KCH_;
    int t = threadIdx.x;                 // 256
    int tx = t & 15, ty = t >> 4;        // 16 x 16; thread tile 4 rows x 2 cols
    float acc[4][2];
    #pragma unroll
    for (int i = 0; i < 4; i++) { acc[i][0] = 0.0f; acc[i][1] = 0.0f; }

    for (int kk = 0; kk < KCH_; kk += KT_) {
        #pragma unroll
        for (int i = 0; i < 2; i++) {
            int e = t + i * 256;
            int r = e >> 3, c = e & 7;
            As[c][r] = A[(m0 + r) * G_ + k0 + kk + c];
        }
        {
            int kr = t >> 5, c = t & 31;    // 8 x 32 = 256
            Bs[kr][c] = Bw[(k0 + kk + kr) * GH_ + n0 + c];
        }
        __syncthreads();
        #pragma unroll
        for (int k = 0; k < KT_; k++) {
            float4 a = *(const float4*)&As[k][ty * 4];
            float2 b = *(const float2*)&Bs[k][tx * 2];
            acc[0][0] += a.x * b.x; acc[0][1] += a.x * b.y;
            acc[1][0] += a.y * b.x; acc[1][1] += a.y * b.y;
            acc[2][0] += a.z * b.x; acc[2][1] += a.z * b.y;
            acc[3][0] += a.w * b.x; acc[3][1] += a.w * b.y;
        }
        __syncthreads();
    }
    #pragma unroll
    for (int i = 0; i < 4; i++) {
        float2 v = make_float2(acc[i][0], acc[i][1]);
        *(float2*)&g_part[(ks * BN_ + m0 + ty * 4 + i) * GH_ + n0 + tx * 2] = v;
    }
}

// ---------------- kernel 3: gate (block per sample) + fused planner (last block) ----------------
__global__ void __launch_bounds__(128) k_gate(
    const float* __restrict__ gb1, const float* __restrict__ W2g,
    const float* __restrict__ gb2, float* __restrict__ out_gw) {
    int b = blockIdx.x;
    int t = threadIdx.x;       // 128 : pathway index
    __shared__ float c1s[GH_];
    __shared__ float slog[P_];
    __shared__ int   sc[P_];
    __shared__ int   is_last;

    // split-K reduce + bias + relu (coalesced over t)
    float v = gb1[t];
    #pragma unroll
    for (int ks = 0; ks < KS_; ks++) v += g_part[(ks * BN_ + b) * GH_ + t];
    c1s[t] = fmaxf(v, 0.0f);
    __syncthreads();

    // GEMM2: thread t = pathway t, 4 interleaved accumulators
    float a0 = 0.f, a1 = 0.f, a2 = 0.f, a3 = 0.f;
    #pragma unroll 4
    for (int h = 0; h < GH_; h += 4) {
        a0 += c1s[h + 0] * W2g[(h + 0) * P_ + t];
        a1 += c1s[h + 1] * W2g[(h + 1) * P_ + t];
        a2 += c1s[h + 2] * W2g[(h + 2) * P_ + t];
        a3 += c1s[h + 3] * W2g[(h + 3) * P_ + t];
    }
    slog[t] = gb2[t] + ((a0 + a1) + (a2 + a3));
    __syncthreads();

    // warp 0: top-3 over 128 (4 candidates per lane), ties -> lowest index
    if (t < 32) {
        int lane = t;
        float acc[4]; int idx[4];
        #pragma unroll
        for (int q = 0; q < 4; q++) { acc[q] = slog[q * 32 + lane]; idx[q] = q * 32 + lane; }
        float topv[K_]; int topi[K_];
        #pragma unroll
        for (int k = 0; k < K_; k++) {
            float bv = acc[0]; int bi = idx[0];
            #pragma unroll
            for (int q = 1; q < 4; q++)
                if (acc[q] > bv || (acc[q] == bv && idx[q] < bi)) { bv = acc[q]; bi = idx[q]; }
            #pragma unroll
            for (int s = 16; s > 0; s >>= 1) {
                float ov = __shfl_xor_sync(0xffffffffu, bv, s);
                int   oi = __shfl_xor_sync(0xffffffffu, bi, s);
                if (ov > bv || (ov == bv && oi < bi)) { bv = ov; bi = oi; }
            }
            topv[k] = bv; topi[k] = bi;
            #pragma unroll
            for (int q = 0; q < 4; q++) if (idx[q] == bi) acc[q] = neg_inf();
        }
        if (lane < K_) {
            float gw = 1.0f / (1.0f + expf(-topv[lane]));
            int p = topi[lane];
            out_gw[b * P_ + p] = gw;
            int pos = atomicAdd(&g_pcnt[p], 1);
            g_pl_b[p * BN_ + pos]    = b;
            g_pl_w[p * BN_ + pos]    = gw;
            g_pl_slot[p * BN_ + pos] = lane;
        }
    }
    // fused planner: last finished block builds the item list
    __syncthreads();
    __threadfence();
    if (t == 0) {
        int old = atomicAdd(&g_done, 1);
        is_last = (old == BN_ - 1) ? 1 : 0;
    }
    __syncthreads();
    if (is_last) {
        __threadfence();
        int n = atomicAdd(&g_pcnt[t], 0);    // coherent read
        int cch = (n + SCH_ - 1) / SCH_;
        sc[t] = cch;
        __syncthreads();
        for (int d = 1; d < P_; d <<= 1) {
            int vv = (t >= d) ? sc[t - d] : 0;
            __syncthreads();
            sc[t] += vv;
            __syncthreads();
        }
        int off = sc[t] - cch;
        for (int i = 0; i < cch; i++) { g_item_p[off + i] = t; g_item_c[off + i] = i * SCH_; }
        if (t == P_ - 1) g_nitems = sc[t];
    }
}

// ---------------- kernel 4: expert partial (fused gather + streaming FMA) ----------------
__global__ void __launch_bounds__(256) k_expert_part(
    const float* __restrict__ xr, const float* __restrict__ xc, const float* __restrict__ xm,
    const float* __restrict__ W1)
{
    int item = blockIdx.x;
    if (item >= g_nitems) return;
    int rs   = blockIdx.y;               // 0..5
    int p    = g_item_p[item];
    int base = g_item_c[item];
    int cnt  = g_pcnt[p];
    int ns   = min(SCH_, max(0, cnt - base));
    int R    = min(3 * g_gcnt[p], R3MAX_);
    int chunk = (R + RS_ - 1) / RS_;
    int r0 = rs * chunk;
    int r1 = min(R, r0 + chunk);
    int n  = r1 - r0;

    int t  = threadIdx.x;          // 256
    int j2 = t & 31;               // h pair: h = j2*2 + {0,1}
    int rg = t >> 5;               // 8 row groups

    __shared__ int   sd[SPLITMAX_];
    __shared__ int   sb[SCH_];
    // overlay: sx (staging+compute) vs red (reduction after compute)
    __shared__ __align__(16) unsigned char sraw[16384];
    float (*sx)[SCH_]      = (float(*)[SCH_])sraw;        // [SPLITMAX_][8] = 12800 B
    float (*red)[SCH_][H_] = (float(*)[SCH_][H_])sraw;    // [8][8][64]    = 16384 B

    if (n <= 0 || ns <= 0) {             // must still clear stale partials
        for (int u = t; u < SCH_ * H_; u += 256) {
            int s = u >> 6, h = u & 63;
            g_hpart[((item * RS_ + rs) * SCH_ + s) * H_ + h] = 0.0f;
        }
        return;
    }

    if (t < SCH_) sb[t] = (t < ns) ? g_pl_b[p * BN_ + base + t] : 0;
    for (int i = t; i < n; i += 256) sd[i] = g_rowd[p * D_ + r0 + i];
    __syncthreads();

    // stage x: scattered reads, coalesced-ish; ~7 independent loads per thread
    for (int e = t; e < n * SCH_; e += 256) {
        int r = e >> 3, s = e & 7;
        float v = 0.0f;
        if (s < ns) {
            int d = sd[r];
            int o = (d >= G_) + (d >= 2 * G_);
            const float* xo = (o == 0) ? xr : ((o == 1) ? xc : xm);
            v = xo[sb[s] * G_ + d - o * G_];
        }
        sx[r][s] = v;
    }
    __syncthreads();

    float acc[2][SCH_];
    #pragma unroll
    for (int hh = 0; hh < 2; hh++)
        #pragma unroll
        for (int s = 0; s < SCH_; s++) acc[hh][s] = 0.0f;

    const float* w1p = W1 + (long)p * (D_ * H_);

    int i = rg;
    for (; i + 8 < n; i += 16) {
        int d0 = sd[i], d1 = sd[i + 8];
        float2 w0 = *(const float2*)&w1p[(long)d0 * H_ + j2 * 2];
        float2 w1 = *(const float2*)&w1p[(long)d1 * H_ + j2 * 2];
        float4 xa0 = *(const float4*)&sx[i][0];
        float4 xb0 = *(const float4*)&sx[i][4];
        float4 xa1 = *(const float4*)&sx[i + 8][0];
        float4 xb1 = *(const float4*)&sx[i + 8][4];
        acc[0][0] += w0.x * xa0.x; acc[0][1] += w0.x * xa0.y; acc[0][2] += w0.x * xa0.z; acc[0][3] += w0.x * xa0.w;
        acc[0][4] += w0.x * xb0.x; acc[0][5] += w0.x * xb0.y; acc[0][6] += w0.x * xb0.z; acc[0][7] += w0.x * xb0.w;
        acc[1][0] += w0.y * xa0.x; acc[1][1] += w0.y * xa0.y; acc[1][2] += w0.y * xa0.z; acc[1][3] += w0.y * xa0.w;
        acc[1][4] += w0.y * xb0.x; acc[1][5] += w0.y * xb0.y; acc[1][6] += w0.y * xb0.z; acc[1][7] += w0.y * xb0.w;
        acc[0][0] += w1.x * xa1.x; acc[0][1] += w1.x * xa1.y; acc[0][2] += w1.x * xa1.z; acc[0][3] += w1.x * xa1.w;
        acc[0][4] += w1.x * xb1.x; acc[0][5] += w1.x * xb1.y; acc[0][6] += w1.x * xb1.z; acc[0][7] += w1.x * xb1.w;
        acc[1][0] += w1.y * xa1.x; acc[1][1] += w1.y * xa1.y; acc[1][2] += w1.y * xa1.z; acc[1][3] += w1.y * xa1.w;
        acc[1][4] += w1.y * xb1.x; acc[1][5] += w1.y * xb1.y; acc[1][6] += w1.y * xb1.z; acc[1][7] += w1.y * xb1.w;
    }
    for (; i < n; i += 8) {
        int d0 = sd[i];
        float2 w0 = *(const float2*)&w1p[(long)d0 * H_ + j2 * 2];
        float4 xa0 = *(const float4*)&sx[i][0];
        float4 xb0 = *(const float4*)&sx[i][4];
        acc[0][0] += w0.x * xa0.x; acc[0][1] += w0.x * xa0.y; acc[0][2] += w0.x * xa0.z; acc[0][3] += w0.x * xa0.w;
        acc[0][4] += w0.x * xb0.x; acc[0][5] += w0.x * xb0.y; acc[0][6] += w0.x * xb0.z; acc[0][7] += w0.x * xb0.w;
        acc[1][0] += w0.y * xa0.x; acc[1][1] += w0.y * xa0.y; acc[1][2] += w0.y * xa0.z; acc[1][3] += w0.y * xa0.w;
        acc[1][4] += w0.y * xb0.x; acc[1][5] += w0.y * xb0.y; acc[1][6] += w0.y * xb0.z; acc[1][7] += w0.y * xb0.w;
    }

    __syncthreads();   // all sx reads done before red overlays it

    #pragma unroll
    for (int s = 0; s < SCH_; s++) {
        red[rg][s][j2 * 2 + 0] = acc[0][s];
        red[rg][s][j2 * 2 + 1] = acc[1][s];
    }
    __syncthreads();

    for (int u = t; u < SCH_ * H_; u += 256) {
        int s = u >> 6, h = u & 63;
        float sum = 0.0f;
        #pragma unroll
        for (int g = 0; g < 8; g++) sum += red[g][s][h];
        g_hpart[((item * RS_ + rs) * SCH_ + s) * H_ + h] = sum;
    }
}

// ---------------- kernel 5: expert finish + fused classifier (last block) ----------------
__global__ void __launch_bounds__(128) k_expert_fin(
    const float* __restrict__ eb1,
    const float* __restrict__ gamma, const float* __restrict__ beta,
    const float* __restrict__ mean,  const float* __restrict__ var,
    const float* __restrict__ W2,    const float* __restrict__ eb2,
    const float* __restrict__ cw1,   const float* __restrict__ cb1,
    const float* __restrict__ cw2,   const float* __restrict__ cb2,
    float* __restrict__ out_logits)
{
    int item = blockIdx.x;
    int t = threadIdx.x;   // 128
    __shared__ int   sb[SCH_];
    __shared__ float swt[SCH_];
    __shared__ int   sslot[SCH_];
    __shared__ float hsh[SCH_][H_];
    __shared__ int   is_last;

    int active = (item < g_nitems);
    int p = 0, base = 0, ns = 0;
    if (active) {
        p    = g_item_p[item];
        base = g_item_c[item];
        int cnt = g_pcnt[p];
        ns = min(SCH_, max(0, cnt - base));
        if (ns == 0) active = 0;
    }

    if (active) {
        if (t < SCH_ && t < ns) {
            sb[t]    = g_pl_b[p * BN_ + base + t];
            swt[t]   = g_pl_w[p * BN_ + base + t];
            sslot[t] = g_pl_slot[p * BN_ + base + t];
        }
        __syncthreads();

        if (t < H_) {
            float b1v = eb1[p * H_ + t];
            float mn  = mean[p * H_ + t];
            float sc  = gamma[p * H_ + t] * rsqrtf(var[p * H_ + t] + EPS_);
            float bt  = beta[p * H_ + t];
            #pragma unroll
            for (int s = 0; s < SCH_; s++) {
                float hv = b1v;
                #pragma unroll
                for (int rs = 0; rs < RS_; rs++)
                    hv += g_hpart[((item * RS_ + rs) * SCH_ + s) * H_ + t];
                hv = (hv - mn) * sc + bt;
                hsh[s][t] = fmaxf(hv, 0.0f);
            }
        }
        __syncthreads();

        if (t < SCH_ * O_) {
            int s = t >> 4, o = t & 15;
            if (s < ns) {
                float a = eb2[p * O_ + o];
                #pragma unroll 8
                for (int jj = 0; jj < H_; jj++) a += hsh[s][jj] * W2[(p * H_ + jj) * O_ + o];
                g_contrib[(sb[s] * K_ + sslot[s]) * O_ + o] = swt[s] * a;
            }
        }
        __syncthreads();
    }

    // completion counting (all blocks, incl. inactive)
    __threadfence();
    if (t == 0) {
        int old = atomicAdd(&g_done2, 1);
        is_last = (old == (int)gridDim.x - 1) ? 1 : 0;
    }
    __syncthreads();
    if (is_last) {
        __threadfence();
        for (int b = t; b < BN_; b += 128) {
            float f[O_];
            #pragma unroll
            for (int o = 0; o < O_; o++)
                f[o] = g_contrib[(b * K_ + 0) * O_ + o]
                     + g_contrib[(b * K_ + 1) * O_ + o]
                     + g_contrib[(b * K_ + 2) * O_ + o];
            float hc[CH_];
            #pragma unroll
            for (int c = 0; c < CH_; c++) {
                float a = cb1[c];
                #pragma unroll
                for (int o = 0; o < O_; o++) a += f[o] * cw1[o * CH_ + c];
                hc[c] = fmaxf(a, 0.0f);
            }
            #pragma unroll
            for (int c = 0; c < C_; c++) {
                float a = cb2[c];
                #pragma unroll
                for (int h = 0; h < CH_; h++) a += hc[h] * cw2[h * C_ + c];
                out_logits[b * C_ + c] = a;
            }
        }
    }
}

// ---------------- launch ----------------
extern "C" void kernel_launch(void* const* d_in, const int* in_sizes, int n_in,
                              void* d_out, int out_size) {
    const float* x_rna     = (const float*)d_in[0];
    const float* x_cnv     = (const float*)d_in[1];
    const float* x_met     = (const float*)d_in[2];
    const float* gene_mask = (const float*)d_in[3];
    const float* gate_w1   = (const float*)d_in[4];
    const float* gate_b1   = (const float*)d_in[5];
    const float* gate_w2   = (const float*)d_in[6];
    const float* gate_b2   = (const float*)d_in[7];
    const float* W1        = (const float*)d_in[8];
    const float* eb1       = (const float*)d_in[9];
    const float* bn_gamma  = (const float*)d_in[10];
    const float* bn_beta   = (const float*)d_in[11];
    const float* bn_mean   = (const float*)d_in[12];
    const float* bn_var    = (const float*)d_in[13];
    const float* W2        = (const float*)d_in[14];
    const float* eb2       = (const float*)d_in[15];
    const float* cls_w1    = (const float*)d_in[16];
    const float* cls_b1    = (const float*)d_in[17];
    const float* cls_w2    = (const float*)d_in[18];
    const float* cls_b2    = (const float*)d_in[19];

    float* out        = (float*)d_out;
    float* out_logits = out;             // [B, C] first (tuple order)
    float* out_gw     = out + BN_ * C_;  // [B, P]

    int total_out = BN_ * C_ + BN_ * P_;
    if (total_out > out_size) total_out = out_size;
    int zb = (total_out + 255) / 256;

    k_pre<<<P_ + zb, 256>>>(gene_mask, out, total_out);                 // 1
    dim3 g1(BN_ / TM_, GH_ / TN_, KS_);
    k_gemm1<<<g1, 256>>>(x_rna, gate_w1);                               // 2
    k_gate<<<BN_, 128>>>(gate_b1, gate_w2, gate_b2, out_gw);            // 3
    dim3 ge(MAXITEMS_, RS_);
    k_expert_part<<<ge, 256>>>(x_rna, x_cnv, x_met, W1);                // 4  <- profiled slot
    k_expert_fin<<<MAXITEMS_, 128>>>(eb1, bn_gamma, bn_beta, bn_mean, bn_var, W2, eb2,
                                     cls_w1, cls_b1, cls_w2, cls_b2, out_logits);  // 5
}